// round 6
// baseline (speedup 1.0000x reference)
#include <cuda_runtime.h>
#include <cstdint>

#define BATCH 256
#define L 4096
#define H 128

// ---------- packed f32x2 helpers (Blackwell sm_103a) ----------
__device__ __forceinline__ uint64_t pack2f(float a, float b) {
    uint64_t r; asm("mov.b64 %0, {%1, %2};" : "=l"(r) : "f"(a), "f"(b)); return r;
}
__device__ __forceinline__ float hsum2(uint64_t v) {
    float a, b; asm("mov.b64 {%0, %1}, %2;" : "=f"(a), "=f"(b) : "l"(v)); return a + b;
}
__device__ __forceinline__ uint64_t ffma2(uint64_t a, uint64_t b, uint64_t c) {
    uint64_t d; asm("fma.rn.f32x2 %0, %1, %2, %3;" : "=l"(d) : "l"(a), "l"(b), "l"(c)); return d;
}
__device__ __forceinline__ uint64_t fadd2(uint64_t a, uint64_t b) {
    uint64_t d; asm("add.rn.f32x2 %0, %1, %2;" : "=l"(d) : "l"(a), "l"(b)); return d;
}
// branchless elu
__device__ __forceinline__ float elu1(float x) {
    return fmaxf(x, 0.f) + (__expf(fminf(x, 0.f)) - 1.f);
}

// One CTA = ONE batch element, 256 threads = (i, s):
//   i = tid>>1 in [0,128): hidden unit;  s = tid&1: k-half owner.
// Thread (i,s) holds its k-half of BOTH layers' W_c columns (32 packed regs)
// -> ~100 regs/thread, fits __launch_bounds__(256,2): TWO CTAs per SM, i.e.
// two fully independent recurrences per SMSP to hide each other's serial tails.
// Per step: one fused loop accumulates layer-1 AND layer-2 half-dots; the two
// k-halves meet via one shfl_xor(1). One __syncthreads per step.
// Output head amortized: per step 1 STS into a 32-slot ring; every 16 steps
// each warp reduces 2 slots (window [t-16, t-1], race-free vs slot t&31).
__global__ void __launch_bounds__(256, 2)
rnn_scan_kernel(const int* __restrict__ x,
                const float* __restrict__ W_in,
                const float* __restrict__ W_c,
                const float* __restrict__ W_out,
                const float* __restrict__ b_out,
                float* __restrict__ out)
{
    __shared__ __align__(16) float sh_h1[2][H];      // [parity][H]
    __shared__ __align__(16) float sh_h2[2][H];
    __shared__ float sh_r[3 * H];                    // r for spin0, spin1, zero-prev
    __shared__ __align__(16) float sh_prod[32][H];   // 16 KB ring of h2*wout
    __shared__ uint8_t sh_x[L];                      // this batch's x (4 KB)
    __shared__ float sh_acc[8];

    const int tid  = threadIdx.x;
    const int warp = tid >> 5;
    const int lane = tid & 31;
    const int i    = tid >> 1;     // hidden unit
    const int s    = tid & 1;      // k-half
    const int b    = blockIdx.x;

    // ---- stage x; precompute r; zero initial state ----
    const int* xg = x + (size_t)b * L;
    #pragma unroll 4
    for (int idx = tid; idx < L; idx += 256) sh_x[idx] = (uint8_t)xg[idx];
    if (tid < 2 * H) sh_r[tid] = elu1(W_in[tid]);
    if (tid < H)     { sh_r[2 * H + tid] = 0.f; sh_h1[0][tid] = 0.f; sh_h2[0][tid] = 0.f; }

    // ---- load W_c half-columns for both layers (packed pairs) ----
    uint64_t w1p[16], w2p[16];
    {
        const float* Wc0 = W_c;
        const float* Wc1 = W_c + H * H;
        #pragma unroll
        for (int j = 0; j < 16; ++j) {
            const int k0 = 8 * j + 4 * s;
            w1p[j]             = pack2f(Wc0[(k0+0)*H + i], Wc0[(k0+1)*H + i]);
            w2p[j]             = pack2f(Wc1[(k0+0)*H + i], Wc1[(k0+1)*H + i]);
        }
    }
    // second pair of each 4-group handled via a second array to keep reg count low
    uint64_t w1q[16], w2q[16];
    {
        const float* Wc0 = W_c;
        const float* Wc1 = W_c + H * H;
        #pragma unroll
        for (int j = 0; j < 16; ++j) {
            const int k0 = 8 * j + 4 * s;
            w1q[j] = pack2f(Wc0[(k0+2)*H + i], Wc0[(k0+3)*H + i]);
            w2q[j] = pack2f(Wc1[(k0+2)*H + i], Wc1[(k0+3)*H + i]);
        }
    }
    const float wout_i = W_out[i];
    const float bout   = b_out[0];
    float acc = 0.f;                 // per-warp partial (lane 0 meaningful)

    __syncthreads();

    for (int t = 0; t < L; ++t) {
        // ===== amortized output head: warp w reduces slots t-16+2w, t-16+2w+1
        if ((t & 15) == 0 && t > 0) {
            #pragma unroll
            for (int e = 0; e < 2; ++e) {
                const int u = t - 16 + 2 * warp + e;
                const float4 v = *(const float4*)&sh_prod[u & 31][lane * 4];
                float sred = (v.x + v.y) + (v.z + v.w);
                #pragma unroll
                for (int off = 16; off; off >>= 1)
                    sred += __shfl_xor_sync(0xffffffffu, sred, off);
                if (lane == 0) {
                    const float logit = sred + bout;
                    const int   xt    = sh_x[u];
                    const float m     = fmaxf(logit, 0.f);
                    const float lse   = m + __logf(__expf(-m) + __expf(logit - m));
                    acc += 0.5f * ((xt ? logit : 0.f) - lse);
                }
            }
        }

        const int p = t & 1;
        const float* h1r = &sh_h1[p][0];
        const float* h2r = &sh_h2[p][0];

        // hoisted spin / r lookup
        const int   prev = t ? (int)sh_x[t - 1] : 2;
        const float rv   = sh_r[prev * H + i];

        // ===== fused layer-1 + layer-2 half-dot =====
        uint64_t a0 = 0, a1 = 0, c0 = 0, c1 = 0;
        #pragma unroll
        for (int j = 0; j < 16; ++j) {
            const int o = 8 * j + 4 * s;
            const ulonglong2 g = *(const ulonglong2*)(h1r + o);
            const ulonglong2 e = *(const ulonglong2*)(h2r + o);
            a0 = ffma2(w1p[j], g.x, a0);
            a1 = ffma2(w1q[j], g.y, a1);
            c0 = ffma2(w2p[j], e.x, c0);
            c1 = ffma2(w2q[j], e.y, c1);
        }
        float d1 = hsum2(fadd2(a0, a1));
        float d2 = hsum2(fadd2(c0, c1));
        d1 += __shfl_xor_sync(0xffffffffu, d1, 1);
        d2 += __shfl_xor_sync(0xffffffffu, d2, 1);

        const float h1n = elu1(d1) + rv;
        const float h2n = elu1(d2) + h1n;
        if (s == 0) {
            sh_h1[p ^ 1][i] = h1n;
        } else {
            sh_h2[p ^ 1][i] = h2n;
            sh_prod[t & 31][i] = h2n * wout_i;
        }

        __syncthreads();   // single barrier per step
    }

    // ===== epilogue: reduce last 16 slots [L-16, L-1] =====
    {
        #pragma unroll
        for (int e = 0; e < 2; ++e) {
            const int u = L - 16 + 2 * warp + e;
            const float4 v = *(const float4*)&sh_prod[u & 31][lane * 4];
            float sred = (v.x + v.y) + (v.z + v.w);
            #pragma unroll
            for (int off = 16; off; off >>= 1)
                sred += __shfl_xor_sync(0xffffffffu, sred, off);
            if (lane == 0) {
                const float logit = sred + bout;
                const int   xt    = sh_x[u];
                const float m     = fmaxf(logit, 0.f);
                const float lse   = m + __logf(__expf(-m) + __expf(logit - m));
                acc += 0.5f * ((xt ? logit : 0.f) - lse);
            }
        }
    }

    if (lane == 0) sh_acc[warp] = acc;
    __syncthreads();
    if (tid == 0) {
        float a = 0.f;
        #pragma unroll
        for (int w = 0; w < 8; ++w) a += sh_acc[w];
        out[b] = a;
    }
}

extern "C" void kernel_launch(void* const* d_in, const int* in_sizes, int n_in,
                              void* d_out, int out_size)
{
    const int*   x     = (const int*)  d_in[0];
    const float* W_in  = (const float*)d_in[1];
    const float* W_c   = (const float*)d_in[2];
    const float* W_out = (const float*)d_in[3];
    const float* b_out = (const float*)d_in[4];

    rnn_scan_kernel<<<BATCH, 256>>>(x, W_in, W_c, W_out, b_out, (float*)d_out);
}

// round 7
// speedup vs baseline: 1.6392x; 1.6392x over previous
#include <cuda_runtime.h>
#include <cstdint>

#define BATCH 256
#define L 4096
#define H 128

// ---------- packed f32x2 helpers (Blackwell sm_103a) ----------
__device__ __forceinline__ uint64_t pack2f(float a, float b) {
    uint64_t r; asm("mov.b64 %0, {%1, %2};" : "=l"(r) : "f"(a), "f"(b)); return r;
}
__device__ __forceinline__ float hsum2(uint64_t v) {
    float a, b; asm("mov.b64 {%0, %1}, %2;" : "=f"(a), "=f"(b) : "l"(v)); return a + b;
}
__device__ __forceinline__ uint64_t ffma2(uint64_t a, uint64_t b, uint64_t c) {
    uint64_t d; asm("fma.rn.f32x2 %0, %1, %2, %3;" : "=l"(d) : "l"(a), "l"(b), "l"(c)); return d;
}
__device__ __forceinline__ uint64_t fadd2(uint64_t a, uint64_t b) {
    uint64_t d; asm("add.rn.f32x2 %0, %1, %2;" : "=l"(d) : "l"(a), "l"(b)); return d;
}
__device__ __forceinline__ uint64_t fmul2(uint64_t a, uint64_t b) {
    uint64_t d; asm("mul.rn.f32x2 %0, %1, %2;" : "=l"(d) : "l"(a), "l"(b)); return d;
}
// branchless elu
__device__ __forceinline__ float elu1(float x) {
    return fmaxf(x, 0.f) + (__expf(fminf(x, 0.f)) - 1.f);
}
__device__ __forceinline__ uint64_t elu2(uint64_t v) {
    float a, b; asm("mov.b64 {%0, %1}, %2;" : "=f"(a), "=f"(b) : "l"(v));
    return pack2f(elu1(a), elu1(b));
}
__device__ __forceinline__ uint64_t shflx2(uint64_t v, int m) {
    uint32_t lo, hi;
    asm("mov.b64 {%0, %1}, %2;" : "=r"(lo), "=r"(hi) : "l"(v));
    lo = __shfl_xor_sync(0xffffffffu, lo, m);
    hi = __shfl_xor_sync(0xffffffffu, hi, m);
    uint64_t r; asm("mov.b64 %0, {%1, %2};" : "=l"(r) : "r"(lo), "r"(hi));
    return r;
}

// One CTA = 2 batch elements, 256 threads = (g, s):
//   g = tid>>2 in [0,64): owns OUTPUT PAIR {2g, 2g+1};  s = tid&3: k-quarter.
// Each 16B h-chunk loaded feeds 4 FFMA2 (2 outputs) -> 32 LDS.128/thread/step
// (half of R4), and each warp LDS touches 4 distinct 16B lines (64B useful per
// wavefront vs 16B broadcast). Weights: 2 outputs x 2 layers x 16 = 64 packed
// regs (same proven budget). Quarter partials meet via shfl_xor(1)+shfl_xor(2).
// One __syncthreads per step; output head amortized in a 32-slot ring.
__global__ void __launch_bounds__(256, 1)
rnn_scan_kernel(const int* __restrict__ x,
                const float* __restrict__ W_in,
                const float* __restrict__ W_c,
                const float* __restrict__ W_out,
                const float* __restrict__ b_out,
                float* __restrict__ out)
{
    __shared__ __align__(16) float sh_h1[2][2 * H];     // [parity][batch*H]
    __shared__ __align__(16) float sh_h2[2][2 * H];
    __shared__ __align__(16) float sh_r[3 * H];         // r for spin0/1, zero-prev
    __shared__ __align__(16) float sh_prod[32][2 * H];  // 32 KB ring: [slot][b*H+o]
    __shared__ uint8_t sh_x[2 * L];                     // x as bytes (8 KB)
    __shared__ float sh_acc[8][2];

    const int tid  = threadIdx.x;
    const int warp = tid >> 5;
    const int lane = tid & 31;
    const int g    = tid >> 2;     // output-pair index: outputs 2g, 2g+1
    const int s    = tid & 3;      // k-quarter
    const int sb   = s & 1;        // batch this thread finalizes
    const int b0   = blockIdx.x * 2;

    // ---- stage x; precompute r; zero initial state ----
    const int* xg = x + (size_t)b0 * L;
    #pragma unroll 4
    for (int idx = tid; idx < 2 * L; idx += 256) sh_x[idx] = (uint8_t)xg[idx];
    if (tid < 2 * H) sh_r[tid] = elu1(W_in[tid]);
    if (tid < H)     sh_r[2 * H + tid] = 0.f;
    if (tid < 2 * H) { sh_h1[0][tid] = 0.f; sh_h2[0][tid] = 0.f; }

    // ---- weights: layer l, output o in {2g,2g+1}, k-quarter s ----
    uint64_t w1[32], w2[32];
    {
        const float* Wc0 = W_c;
        const float* Wc1 = W_c + H * H;
        #pragma unroll
        for (int c = 0; c < 8; ++c) {
            const int k0 = 16 * c + 4 * s;
            const int o0 = 2 * g, o1 = 2 * g + 1;
            w1[4*c+0] = pack2f(Wc0[(k0+0)*H + o0], Wc0[(k0+1)*H + o0]);
            w1[4*c+1] = pack2f(Wc0[(k0+2)*H + o0], Wc0[(k0+3)*H + o0]);
            w1[4*c+2] = pack2f(Wc0[(k0+0)*H + o1], Wc0[(k0+1)*H + o1]);
            w1[4*c+3] = pack2f(Wc0[(k0+2)*H + o1], Wc0[(k0+3)*H + o1]);
            w2[4*c+0] = pack2f(Wc1[(k0+0)*H + o0], Wc1[(k0+1)*H + o0]);
            w2[4*c+1] = pack2f(Wc1[(k0+2)*H + o0], Wc1[(k0+3)*H + o0]);
            w2[4*c+2] = pack2f(Wc1[(k0+0)*H + o1], Wc1[(k0+1)*H + o1]);
            w2[4*c+3] = pack2f(Wc1[(k0+2)*H + o1], Wc1[(k0+3)*H + o1]);
        }
    }
    const uint64_t woutp = pack2f(W_out[2 * g], W_out[2 * g + 1]);
    const float bout = b_out[0];
    float hacc0 = 0.f, hacc1 = 0.f;   // head partials (identical across lanes)

    __syncthreads();

    for (int t = 0; t < L; ++t) {
        // ===== amortized head: window [t-16, t-1]; warp w -> slots t-16+2w,+1, both batches
        if ((t & 15) == 0 && t > 0) {
            #pragma unroll
            for (int e = 0; e < 2; ++e) {
                const int u    = t - 16 + 2 * warp + e;
                const int slot = u & 31;
                #pragma unroll
                for (int b = 0; b < 2; ++b) {
                    const float4 v = *(const float4*)&sh_prod[slot][b * H + lane * 4];
                    float sr = (v.x + v.y) + (v.z + v.w);
                    #pragma unroll
                    for (int off = 16; off; off >>= 1)
                        sr += __shfl_xor_sync(0xffffffffu, sr, off);
                    const float logit = sr + bout;
                    const int   xt    = sh_x[b * L + u];
                    const float m     = fmaxf(logit, 0.f);
                    const float lse   = m + __logf(__expf(-m) + __expf(logit - m));
                    const float gv    = 0.5f * ((xt ? logit : 0.f) - lse);
                    if (b == 0) hacc0 += gv; else hacc1 += gv;
                }
            }
        }

        const int p = t & 1;
        const float* h1r = &sh_h1[p][0];
        float*       h1w = &sh_h1[p ^ 1][0];
        const float* h2r = &sh_h2[p][0];
        float*       h2w = &sh_h2[p ^ 1][0];

        // hoisted spin / r pair (LDS.64) for this thread's batch
        const int prev = t ? (int)sh_x[sb * L + t - 1] : 2;
        const uint64_t rv = *(const uint64_t*)&sh_r[prev * H + 2 * g];

        // ===== fused quarter-dot: 2 layers x 2 batches x 2 outputs =====
        uint64_t a0=0,a1=0,a2=0,a3=0,a4=0,a5=0,a6=0,a7=0;
        #pragma unroll
        for (int c = 0; c < 8; ++c) {
            const int o = 16 * c + 4 * s;
            const ulonglong2 A = *(const ulonglong2*)(h1r + o);       // l1 b0
            const ulonglong2 B = *(const ulonglong2*)(h1r + H + o);   // l1 b1
            const ulonglong2 C = *(const ulonglong2*)(h2r + o);       // l2 b0
            const ulonglong2 D = *(const ulonglong2*)(h2r + H + o);   // l2 b1
            a0 = ffma2(w1[4*c+0], A.x, a0);  a0 = ffma2(w1[4*c+1], A.y, a0);
            a1 = ffma2(w1[4*c+2], A.x, a1);  a1 = ffma2(w1[4*c+3], A.y, a1);
            a2 = ffma2(w1[4*c+0], B.x, a2);  a2 = ffma2(w1[4*c+1], B.y, a2);
            a3 = ffma2(w1[4*c+2], B.x, a3);  a3 = ffma2(w1[4*c+3], B.y, a3);
            a4 = ffma2(w2[4*c+0], C.x, a4);  a4 = ffma2(w2[4*c+1], C.y, a4);
            a5 = ffma2(w2[4*c+2], C.x, a5);  a5 = ffma2(w2[4*c+3], C.y, a5);
            a6 = ffma2(w2[4*c+0], D.x, a6);  a6 = ffma2(w2[4*c+1], D.y, a6);
            a7 = ffma2(w2[4*c+2], D.x, a7);  a7 = ffma2(w2[4*c+3], D.y, a7);
        }

        // per-vector packed dots (outputs paired in f32x2)
        uint64_t v_l1b0 = pack2f(hsum2(a0), hsum2(a1));
        uint64_t v_l1b1 = pack2f(hsum2(a2), hsum2(a3));
        uint64_t v_l2b0 = pack2f(hsum2(a4), hsum2(a5));
        uint64_t v_l2b1 = pack2f(hsum2(a6), hsum2(a7));

        // reduce across the 4 k-quarters (xor1 then xor2)
        v_l1b0 = fadd2(v_l1b0, shflx2(v_l1b0, 1));
        v_l1b1 = fadd2(v_l1b1, shflx2(v_l1b1, 1));
        v_l2b0 = fadd2(v_l2b0, shflx2(v_l2b0, 1));
        v_l2b1 = fadd2(v_l2b1, shflx2(v_l2b1, 1));
        v_l1b0 = fadd2(v_l1b0, shflx2(v_l1b0, 2));
        v_l1b1 = fadd2(v_l1b1, shflx2(v_l1b1, 2));
        v_l2b0 = fadd2(v_l2b0, shflx2(v_l2b0, 2));
        v_l2b1 = fadd2(v_l2b1, shflx2(v_l2b1, 2));

        // finalize: each thread handles batch sb; s<2 writes h1, s>=2 writes h2+prod
        const uint64_t vl1 = sb ? v_l1b1 : v_l1b0;
        const uint64_t vl2 = sb ? v_l2b1 : v_l2b0;
        const uint64_t h1n = fadd2(elu2(vl1), rv);
        const uint64_t h2n = fadd2(elu2(vl2), h1n);
        if (s < 2) {
            *(uint64_t*)&h1w[sb * H + 2 * g] = h1n;
        } else {
            *(uint64_t*)&h2w[sb * H + 2 * g] = h2n;
            *(uint64_t*)&sh_prod[t & 31][sb * H + 2 * g] = fmul2(h2n, woutp);
        }

        __syncthreads();   // single barrier per step
    }

    // ===== epilogue: reduce last 16 slots [L-16, L-1] =====
    #pragma unroll
    for (int e = 0; e < 2; ++e) {
        const int u    = L - 16 + 2 * warp + e;
        const int slot = u & 31;
        #pragma unroll
        for (int b = 0; b < 2; ++b) {
            const float4 v = *(const float4*)&sh_prod[slot][b * H + lane * 4];
            float sr = (v.x + v.y) + (v.z + v.w);
            #pragma unroll
            for (int off = 16; off; off >>= 1)
                sr += __shfl_xor_sync(0xffffffffu, sr, off);
            const float logit = sr + bout;
            const int   xt    = sh_x[b * L + u];
            const float m     = fmaxf(logit, 0.f);
            const float lse   = m + __logf(__expf(-m) + __expf(logit - m));
            const float gv    = 0.5f * ((xt ? logit : 0.f) - lse);
            if (b == 0) hacc0 += gv; else hacc1 += gv;
        }
    }

    if (lane == 0) { sh_acc[warp][0] = hacc0; sh_acc[warp][1] = hacc1; }
    __syncthreads();
    if (tid < 2) {
        float a = 0.f;
        #pragma unroll
        for (int w = 0; w < 8; ++w) a += sh_acc[w][tid];
        out[b0 + tid] = a;
    }
}

extern "C" void kernel_launch(void* const* d_in, const int* in_sizes, int n_in,
                              void* d_out, int out_size)
{
    const int*   x     = (const int*)  d_in[0];
    const float* W_in  = (const float*)d_in[1];
    const float* W_c   = (const float*)d_in[2];
    const float* W_out = (const float*)d_in[3];
    const float* b_out = (const float*)d_in[4];

    rnn_scan_kernel<<<BATCH / 2, 256>>>(x, W_in, W_c, W_out, b_out, (float*)d_out);
}